// round 14
// baseline (speedup 1.0000x reference)
#include <cuda_runtime.h>
#include <cuda_fp16.h>
#include <mma.h>

using namespace nvcuda;

#define NN 100000
#define EE 1200000
#define HH 64
#define BB 1000
#define CC 10
#define BN_EPS 1e-5f
#define WP 72    // padded row stride (elements) for smem tiles
#define CAP 64   // per-node neighbor bucket capacity (max degree ~29)

typedef unsigned long long u64;

// Scratch (device globals; no allocation allowed).
// NOTE: g_deg and g_xstruct are zero on first use (static init) and are
// reset by agg_kernel<2> / final_kernel at the end of every launch, so each
// graph replay starts from zeroed state without a dedicated zero kernel.
__device__ __align__(16) __half g_xh[NN * HH];       // fp16 shadow of x
__device__ __align__(16) __half g_agg1h[NN * HH];    // fp16 agg of layer 1 input
__device__ __align__(16) __half g_h1bh[NN * HH];     // fp16 output of MLP1
__device__ __align__(16) __half g_agg2h[NN * HH];    // fp16 agg of layer 2 input
__device__ __align__(16) float  g_xstruct[BB * HH];  // pooled per-graph features
__device__ __align__(16) float  g_xtopo[BB * HH];    // relu(topo@Wt+bt)
__device__ int g_deg[NN];
__device__ __align__(16) int g_bucket[(size_t)NN * CAP];  // neighbor lists

__device__ __forceinline__ void red_add_v4(float* p, float4 v) {
    asm volatile("red.global.add.v4.f32 [%0], {%1,%2,%3,%4};"
                 :: "l"(p), "f"(v.x), "f"(v.y), "f"(v.z), "f"(v.w)
                 : "memory");
}

// convert x -> fp16 shadow (independent; runs on side stream)
__global__ void convert_kernel(const float* __restrict__ x) {
    int i = blockIdx.x * 256 + threadIdx.x;
    if (i < NN * HH / 4) {
        float4 v = *(const float4*)(x + (size_t)i * 4);
        __half2 h0 = __floats2half2_rn(v.x, v.y);
        __half2 h1 = __floats2half2_rn(v.z, v.w);
        uint2 u;
        u.x = *(unsigned*)&h0;
        u.y = *(unsigned*)&h1;
        *(uint2*)(g_xh + (size_t)i * 4) = u;
    }
}

// topo branch: g_xtopo = relu(topo @ Wt + bt)  (independent; side stream)
__global__ __launch_bounds__(256) void topo_kernel(
    const float* __restrict__ topo, const float* __restrict__ Wt,
    const float* __restrict__ bt)
{
    __shared__ float Wts[64 * 64];
    __shared__ float bts[64];
    __shared__ float trow[4][64];

    const int tx = threadIdx.x;   // 0..63
    const int ty = threadIdx.y;   // 0..3
    const int tid = ty * 64 + tx;

    for (int i = tid; i < 4096; i += 256) Wts[i] = Wt[i];
    if (tid < 64) bts[tid] = bt[tid];
    __syncthreads();

    for (int g0 = blockIdx.x * 4; g0 < BB; g0 += gridDim.x * 4) {
        int g = g0 + ty;
        bool valid = g < BB;
        if (valid) trow[ty][tx] = topo[g * 64 + tx];
        __syncthreads();
        if (valid) {
            float acc = bts[tx];
            #pragma unroll 16
            for (int k = 0; k < 64; k++)
                acc += trow[ty][k] * Wts[k * 64 + tx];
            g_xtopo[g * 64 + tx] = fmaxf(acc, 0.f);
        }
        __syncthreads();
    }
}

// fill: histogram + direct bucket placement (g_deg zeroed by prior launch)
__global__ void fill_kernel(const int* __restrict__ ei) {
    int e = blockIdx.x * 256 + threadIdx.x;
    if (e < EE) {
        int s = ei[e];
        int d = ei[EE + e];
        int pos = atomicAdd(&g_deg[d], 1);
        if (pos < CAP)
            g_bucket[(size_t)d * CAP + pos] = s;
    }
}

// ---------------------------------------------------------------------------
// Pull aggregation: 8 threads/node, fp16 gather, pairwise HADD2 pre-add,
// fp32 master accumulate, fp16 output. int4 bucket-index loads.
// LAYER==2 additionally resets g_deg for the next launch.
// ---------------------------------------------------------------------------
__device__ __forceinline__ void acc_half8(float* acc, const __half* p) {
    uint4 u = *(const uint4*)p;
    __half2* h = (__half2*)&u;
    #pragma unroll
    for (int i = 0; i < 4; i++) {
        float2 f = __half22float2(h[i]);
        acc[2 * i]     += f.x;
        acc[2 * i + 1] += f.y;
    }
}

__device__ __forceinline__ void acc_pair_half8(float* acc, const __half* pa,
                                               const __half* pb) {
    uint4 ua = *(const uint4*)pa;
    uint4 ub = *(const uint4*)pb;
    __half2* ha = (__half2*)&ua;
    __half2* hb = (__half2*)&ub;
    #pragma unroll
    for (int i = 0; i < 4; i++) {
        __half2 s = __hadd2(ha[i], hb[i]);
        float2 f = __half22float2(s);
        acc[2 * i]     += f.x;
        acc[2 * i + 1] += f.y;
    }
}

__device__ __forceinline__ void store_half8(__half* p, const float* acc) {
    uint4 u;
    unsigned* w = (unsigned*)&u;
    #pragma unroll
    for (int i = 0; i < 4; i++) {
        __half2 h = __floats2half2_rn(acc[2 * i], acc[2 * i + 1]);
        w[i] = *(unsigned*)&h;
    }
    *(uint4*)p = u;
}

template<int LAYER>
__global__ __launch_bounds__(256) void agg_kernel()
{
    const __half* __restrict__ SRC = (LAYER == 1) ? g_xh    : g_h1bh;
    __half* __restrict__       DST = (LAYER == 1) ? g_agg1h : g_agg2h;

    int tid = blockIdx.x * 256 + threadIdx.x;
    int node = tid >> 3;
    if (node >= NN) return;
    int c = (tid & 7) * 8;

    float acc[8] = {0.f, 0.f, 0.f, 0.f, 0.f, 0.f, 0.f, 0.f};
    acc_half8(acc, SRC + (size_t)node * 64 + c);   // self
    int deg = g_deg[node];
    if (deg > CAP) deg = CAP;
    const int* bkt = g_bucket + (size_t)node * CAP;

    if (LAYER == 2) {
        // reset for next launch; load above already issued for all lanes
        if ((tid & 7) == 0) g_deg[node] = 0;
    }

    int j = 0;
    for (; j + 3 < deg; j += 4) {
        int4 s = *(const int4*)(bkt + j);   // 16B-aligned (j%4==0, CAP%4==0)
        acc_pair_half8(acc, SRC + (size_t)s.x * 64 + c, SRC + (size_t)s.y * 64 + c);
        acc_pair_half8(acc, SRC + (size_t)s.z * 64 + c, SRC + (size_t)s.w * 64 + c);
    }
    if (j + 1 < deg) {
        int s0 = bkt[j], s1 = bkt[j + 1];
        acc_pair_half8(acc, SRC + (size_t)s0 * 64 + c, SRC + (size_t)s1 * 64 + c);
        j += 2;
    }
    if (j < deg)
        acc_half8(acc, SRC + (size_t)bkt[j] * 64 + c);
    store_half8(DST + (size_t)node * 64 + c, acc);
}

// ---------------------------------------------------------------------------
// MLP1 (wmma, 256 thr, padded smem): h1bh = fp16(relu(relu(BN(agg1@W1a+b1a))@W1b+b1b))
// ---------------------------------------------------------------------------
__global__ __launch_bounds__(256) void mlp1_kernel(
    const float* __restrict__ W1a, const float* __restrict__ b1a,
    const float* __restrict__ g1,  const float* __restrict__ be1,
    const float* __restrict__ m1,  const float* __restrict__ v1,
    const float* __restrict__ W1b, const float* __restrict__ b1b)
{
    extern __shared__ char smraw[];
    __half* Wa  = (__half*)smraw;              // 64 x WP
    __half* Wb  = Wa + 64 * WP;                // 64 x WP
    __half* Ah  = Wb + 64 * WP;                // 128 x WP
    float*  Mid = (float*)(Ah + 128 * WP);     // 128 x WP
    __shared__ float bias1[64], bias2[64], scl[64];

    const int tid = threadIdx.x;
    const int w   = tid >> 5;

    if (tid < 64) {
        float s = g1[tid] * rsqrtf(v1[tid] + BN_EPS);
        scl[tid]   = s;
        bias1[tid] = b1a[tid] * s + be1[tid] - m1[tid] * s;
        bias2[tid] = b1b[tid];
    }
    __syncthreads();
    for (int i = tid; i < 4096; i += 256) {
        int r = i >> 6, c = i & 63;
        Wa[r * WP + c] = __float2half(W1a[i] * scl[c]);
        Wb[r * WP + c] = __float2half(W1b[i]);
    }
    __syncthreads();

    for (int n0 = blockIdx.x * 128; n0 < NN; n0 += gridDim.x * 128) {
        #pragma unroll
        for (int i = 0; i < 4; i++) {
            int idx = tid + i * 256;
            int row = idx >> 3, q = idx & 7;
            int node = n0 + row;
            uint4 v = make_uint4(0, 0, 0, 0);
            if (node < NN) v = ((const uint4*)g_agg1h)[(size_t)node * 8 + q];
            *(uint4*)(Ah + row * WP + q * 8) = v;
        }
        __syncthreads();

        // ---- layer 1 ----
        {
            wmma::fragment<wmma::accumulator, 16, 16, 16, float> acc[4];
            #pragma unroll
            for (int c = 0; c < 4; c++) wmma::fill_fragment(acc[c], 0.f);
            #pragma unroll
            for (int kk = 0; kk < 4; kk++) {
                wmma::fragment<wmma::matrix_a, 16, 16, 16, __half, wmma::row_major> a;
                wmma::load_matrix_sync(a, Ah + (w * 16) * WP + kk * 16, WP);
                #pragma unroll
                for (int c = 0; c < 4; c++) {
                    wmma::fragment<wmma::matrix_b, 16, 16, 16, __half, wmma::row_major> b;
                    wmma::load_matrix_sync(b, Wa + (kk * 16) * WP + c * 16, WP);
                    wmma::mma_sync(acc[c], a, b, acc[c]);
                }
            }
            #pragma unroll
            for (int c = 0; c < 4; c++)
                wmma::store_matrix_sync(Mid + (w * 16) * WP + c * 16, acc[c],
                                        WP, wmma::mem_row_major);
        }
        __syncthreads();

        // bias + relu + fp16 -> Ah
        #pragma unroll
        for (int i = 0; i < 16; i++) {
            int s = tid + i * 256;
            int row = s >> 5, col2 = s & 31;
            float lo = fmaxf(Mid[row * WP + 2 * col2]     + bias1[2 * col2],     0.f);
            float hi = fmaxf(Mid[row * WP + 2 * col2 + 1] + bias1[2 * col2 + 1], 0.f);
            *(__half2*)(Ah + row * WP + 2 * col2) = __floats2half2_rn(lo, hi);
        }
        __syncthreads();

        // ---- layer 2 ----
        {
            wmma::fragment<wmma::accumulator, 16, 16, 16, float> acc[4];
            #pragma unroll
            for (int c = 0; c < 4; c++) wmma::fill_fragment(acc[c], 0.f);
            #pragma unroll
            for (int kk = 0; kk < 4; kk++) {
                wmma::fragment<wmma::matrix_a, 16, 16, 16, __half, wmma::row_major> a;
                wmma::load_matrix_sync(a, Ah + (w * 16) * WP + kk * 16, WP);
                #pragma unroll
                for (int c = 0; c < 4; c++) {
                    wmma::fragment<wmma::matrix_b, 16, 16, 16, __half, wmma::row_major> b;
                    wmma::load_matrix_sync(b, Wb + (kk * 16) * WP + c * 16, WP);
                    wmma::mma_sync(acc[c], a, b, acc[c]);
                }
            }
            #pragma unroll
            for (int c = 0; c < 4; c++)
                wmma::store_matrix_sync(Mid + (w * 16) * WP + c * 16, acc[c],
                                        WP, wmma::mem_row_major);
        }
        __syncthreads();

        // epilogue: bias + relu -> fp16 gmem
        #pragma unroll
        for (int i = 0; i < 16; i++) {
            int s = tid + i * 256;
            int row = s >> 5, col2 = s & 31;
            int node = n0 + row;
            if (node < NN) {
                float lo = fmaxf(Mid[row * WP + 2 * col2]     + bias2[2 * col2],     0.f);
                float hi = fmaxf(Mid[row * WP + 2 * col2 + 1] + bias2[2 * col2 + 1], 0.f);
                ((__half2*)g_h1bh)[(size_t)node * 32 + col2] = __floats2half2_rn(lo, hi);
            }
        }
        __syncthreads();
    }
}

// ---------------------------------------------------------------------------
// MLP2 (wmma, 256 thr, padded smem) + pooling
// ---------------------------------------------------------------------------
__global__ __launch_bounds__(256) void mlp2_kernel(
    const float* __restrict__ W2, const float* __restrict__ b2,
    const float* __restrict__ g2, const float* __restrict__ be2,
    const float* __restrict__ m2, const float* __restrict__ v2,
    const int* __restrict__ batch)
{
    extern __shared__ char smraw[];
    __half* Ws  = (__half*)smraw;              // 64 x WP
    __half* Ah  = Ws + 64 * WP;                // 128 x WP
    float*  Mid = (float*)(Ah + 128 * WP);     // 128 x WP
    __shared__ float bias[64], scl[64];

    const int tid = threadIdx.x;
    const int w   = tid >> 5;

    if (tid < 64) {
        float s = g2[tid] * rsqrtf(v2[tid] + BN_EPS);
        scl[tid]  = s;
        bias[tid] = b2[tid] * s + be2[tid] - m2[tid] * s;
    }
    __syncthreads();
    for (int i = tid; i < 4096; i += 256) {
        int r = i >> 6, c = i & 63;
        Ws[r * WP + c] = __float2half(W2[i] * scl[c]);
    }
    __syncthreads();

    for (int n0 = blockIdx.x * 128; n0 < NN; n0 += gridDim.x * 128) {
        #pragma unroll
        for (int i = 0; i < 4; i++) {
            int idx = tid + i * 256;
            int row = idx >> 3, q = idx & 7;
            int node = n0 + row;
            uint4 v = make_uint4(0, 0, 0, 0);
            if (node < NN) v = ((const uint4*)g_agg2h)[(size_t)node * 8 + q];
            *(uint4*)(Ah + row * WP + q * 8) = v;
        }
        __syncthreads();

        {
            wmma::fragment<wmma::accumulator, 16, 16, 16, float> acc[4];
            #pragma unroll
            for (int c = 0; c < 4; c++) wmma::fill_fragment(acc[c], 0.f);
            #pragma unroll
            for (int kk = 0; kk < 4; kk++) {
                wmma::fragment<wmma::matrix_a, 16, 16, 16, __half, wmma::row_major> a;
                wmma::load_matrix_sync(a, Ah + (w * 16) * WP + kk * 16, WP);
                #pragma unroll
                for (int c = 0; c < 4; c++) {
                    wmma::fragment<wmma::matrix_b, 16, 16, 16, __half, wmma::row_major> b;
                    wmma::load_matrix_sync(b, Ws + (kk * 16) * WP + c * 16, WP);
                    wmma::mma_sync(acc[c], a, b, acc[c]);
                }
            }
            #pragma unroll
            for (int c = 0; c < 4; c++)
                wmma::store_matrix_sync(Mid + (w * 16) * WP + c * 16, acc[c],
                                        WP, wmma::mem_row_major);
        }
        __syncthreads();

        // pooling epilogue: bias + relu -> red.add float4
        #pragma unroll
        for (int i = 0; i < 8; i++) {
            int s = tid + i * 256;
            int row = s >> 4, fq = s & 15;
            int node = n0 + row;
            if (node < NN) {
                const float* m = Mid + row * WP + fq * 4;
                float4 v;
                v.x = fmaxf(m[0] + bias[fq * 4],     0.f);
                v.y = fmaxf(m[1] + bias[fq * 4 + 1], 0.f);
                v.z = fmaxf(m[2] + bias[fq * 4 + 2], 0.f);
                v.w = fmaxf(m[3] + bias[fq * 4 + 3], 0.f);
                int g = batch[node];
                red_add_v4(g_xstruct + (size_t)g * 64 + fq * 4, v);
            }
        }
        __syncthreads();
    }
}

// ---------------------------------------------------------------------------
// K6: classifier only: out = [xstruct, xtopo] @ Wc + bc.
// Resets g_xstruct after reading (state for next launch).
// ---------------------------------------------------------------------------
__global__ __launch_bounds__(256) void final_kernel(
    const float* __restrict__ Wc, const float* __restrict__ bc,
    float* __restrict__ out)
{
    __shared__ float Wcs[128 * CC];
    __shared__ float bcs[CC];
    __shared__ float xt[4][64];
    __shared__ float xs[4][64];

    const int tx = threadIdx.x;   // 0..63
    const int ty = threadIdx.y;   // 0..3
    const int tid = ty * 64 + tx;

    for (int i = tid; i < 128 * CC; i += 256) Wcs[i] = Wc[i];
    if (tid < CC) bcs[tid] = bc[tid];
    __syncthreads();

    for (int g0 = blockIdx.x * 4; g0 < BB; g0 += gridDim.x * 4) {
        int g = g0 + ty;
        bool valid = g < BB;
        if (valid) {
            xs[ty][tx] = g_xstruct[g * 64 + tx];
            xt[ty][tx] = g_xtopo[g * 64 + tx];
            g_xstruct[g * 64 + tx] = 0.0f;   // reset for next launch
        }
        __syncthreads();
        if (valid && tx < CC) {
            float acc = bcs[tx];
            #pragma unroll 16
            for (int k = 0; k < 64; k++) {
                acc += xs[ty][k] * Wcs[k * CC + tx];
                acc += xt[ty][k] * Wcs[(64 + k) * CC + tx];
            }
            out[g * CC + tx] = acc;
        }
        __syncthreads();
    }
}

// ---------------------------------------------------------------------------
extern "C" void kernel_launch(void* const* d_in, const int* in_sizes, int n_in,
                              void* d_out, int out_size) {
    const float* x    = (const float*)d_in[0];
    const int*   ei   = (const int*)d_in[1];
    const int*   batch= (const int*)d_in[2];
    const float* topo = (const float*)d_in[3];
    const float* W1a  = (const float*)d_in[4];
    const float* b1a  = (const float*)d_in[5];
    const float* g1   = (const float*)d_in[6];
    const float* be1  = (const float*)d_in[7];
    const float* m1   = (const float*)d_in[8];
    const float* v1   = (const float*)d_in[9];
    const float* W1b  = (const float*)d_in[10];
    const float* b1b  = (const float*)d_in[11];
    const float* W2   = (const float*)d_in[12];
    const float* b2   = (const float*)d_in[13];
    const float* g2   = (const float*)d_in[14];
    const float* be2  = (const float*)d_in[15];
    const float* m2   = (const float*)d_in[16];
    const float* v2   = (const float*)d_in[17];
    const float* Wt   = (const float*)d_in[18];
    const float* bt   = (const float*)d_in[19];
    const float* Wc   = (const float*)d_in[20];
    const float* bc   = (const float*)d_in[21];
    float* out = (float*)d_out;

    const int smem1 = (64 * WP * 2 + 128 * WP) * 2 + 128 * WP * 4;  // ~74 KB
    const int smem2 = (64 * WP + 128 * WP) * 2 + 128 * WP * 4;      // ~65 KB

    static cudaStream_t s2;
    static cudaEvent_t evFork, evJoin;
    static bool init_done = false;
    if (!init_done) {
        cudaFuncSetAttribute(mlp1_kernel,
                             cudaFuncAttributeMaxDynamicSharedMemorySize, smem1);
        cudaFuncSetAttribute(mlp2_kernel,
                             cudaFuncAttributeMaxDynamicSharedMemorySize, smem2);
        cudaStreamCreateWithFlags(&s2, cudaStreamNonBlocking);
        cudaEventCreateWithFlags(&evFork, cudaEventDisableTiming);
        cudaEventCreateWithFlags(&evJoin, cudaEventDisableTiming);
        init_done = true;
    }

    dim3 b64x4(64, 4);

    // Fork: fp16 conversion + topo branch run concurrently with bucket build
    cudaEventRecord(evFork, 0);
    cudaStreamWaitEvent(s2, evFork, 0);
    convert_kernel<<<(NN * HH / 4 + 255) / 256, 256, 0, s2>>>(x);
    topo_kernel<<<64, b64x4, 0, s2>>>(topo, Wt, bt);
    cudaEventRecord(evJoin, s2);

    // Bucket build (main stream). g_deg zeroed by previous launch / static init.
    fill_kernel<<<(EE + 255) / 256, 256>>>(ei);

    // Join before layer 1 (needs g_xh; g_xtopo needed only by final)
    cudaStreamWaitEvent(0, evJoin, 0);

    // Layer 1
    agg_kernel<1><<<(NN * 8 + 255) / 256, 256>>>();
    mlp1_kernel<<<782, 256, smem1>>>(W1a, b1a, g1, be1, m1, v1, W1b, b1b);

    // Layer 2 (agg2 also resets g_deg)
    agg_kernel<2><<<(NN * 8 + 255) / 256, 256>>>();
    mlp2_kernel<<<782, 256, smem2>>>(W2, b2, g2, be2, m2, v2, batch);

    // Classifier (also resets g_xstruct)
    final_kernel<<<64, b64x4>>>(Wc, bc, out);
}

// round 15
// speedup vs baseline: 1.2043x; 1.2043x over previous
#include <cuda_runtime.h>
#include <cuda_fp16.h>
#include <mma.h>

using namespace nvcuda;

#define NN 100000
#define EE 1200000
#define HH 64
#define BB 1000
#define CC 10
#define BN_EPS 1e-5f
#define WP 72    // padded row stride (elements) for smem tiles
#define CAP 64   // per-node neighbor bucket capacity (max degree ~29)

typedef unsigned long long u64;

// Scratch (device globals; no allocation allowed)
__device__ __align__(16) __half g_xh[NN * HH];       // fp16 shadow of x
__device__ __align__(16) __half g_agg1h[NN * HH];    // fp16 agg of layer 1 input
__device__ __align__(16) __half g_h1bh[NN * HH];     // fp16 output of MLP1
__device__ __align__(16) __half g_agg2h[NN * HH];    // fp16 agg of layer 2 input
__device__ __align__(16) float  g_xstruct[BB * HH];  // pooled per-graph features
__device__ int g_deg[NN];
__device__ __align__(16) int g_bucket[(size_t)NN * CAP];  // neighbor lists

__device__ __forceinline__ void red_add_v4(float* p, float4 v) {
    asm volatile("red.global.add.v4.f32 [%0], {%1,%2,%3,%4};"
                 :: "l"(p), "f"(v.x), "f"(v.y), "f"(v.z), "f"(v.w)
                 : "memory");
}

// ---------------------------------------------------------------------------
// zero: deg + xstruct
// ---------------------------------------------------------------------------
__global__ void zero_kernel() {
    int i = blockIdx.x * 256 + threadIdx.x;
    if (i < NN) g_deg[i] = 0;
    if (i < BB * HH) g_xstruct[i] = 0.0f;
}

// convert x -> fp16 shadow (independent; runs on side stream)
__global__ void convert_kernel(const float* __restrict__ x) {
    int i = blockIdx.x * 256 + threadIdx.x;
    if (i < NN * HH / 4) {
        float4 v = *(const float4*)(x + (size_t)i * 4);
        __half2 h0 = __floats2half2_rn(v.x, v.y);
        __half2 h1 = __floats2half2_rn(v.z, v.w);
        uint2 u;
        u.x = *(unsigned*)&h0;
        u.y = *(unsigned*)&h1;
        *(uint2*)(g_xh + (size_t)i * 4) = u;
    }
}

// fill: histogram + direct bucket placement
__global__ void fill_kernel(const int* __restrict__ ei) {
    int e = blockIdx.x * 256 + threadIdx.x;
    if (e < EE) {
        int s = ei[e];
        int d = ei[EE + e];
        int pos = atomicAdd(&g_deg[d], 1);
        if (pos < CAP)
            g_bucket[(size_t)d * CAP + pos] = s;
    }
}

// ---------------------------------------------------------------------------
// Pull aggregation: 8 threads/node, fp16 gather, pairwise HADD2 pre-add,
// fp32 master accumulate, fp16 output. int4 bucket-index loads.
// launch_bounds(256,8) forces 32-reg budget for full occupancy (latency-bound).
// ---------------------------------------------------------------------------
__device__ __forceinline__ void acc_half8(float* acc, const __half* p) {
    uint4 u = *(const uint4*)p;
    __half2* h = (__half2*)&u;
    #pragma unroll
    for (int i = 0; i < 4; i++) {
        float2 f = __half22float2(h[i]);
        acc[2 * i]     += f.x;
        acc[2 * i + 1] += f.y;
    }
}

__device__ __forceinline__ void acc_pair_half8(float* acc, const __half* pa,
                                               const __half* pb) {
    uint4 ua = *(const uint4*)pa;
    uint4 ub = *(const uint4*)pb;
    __half2* ha = (__half2*)&ua;
    __half2* hb = (__half2*)&ub;
    #pragma unroll
    for (int i = 0; i < 4; i++) {
        __half2 s = __hadd2(ha[i], hb[i]);
        float2 f = __half22float2(s);
        acc[2 * i]     += f.x;
        acc[2 * i + 1] += f.y;
    }
}

__device__ __forceinline__ void store_half8(__half* p, const float* acc) {
    uint4 u;
    unsigned* w = (unsigned*)&u;
    #pragma unroll
    for (int i = 0; i < 4; i++) {
        __half2 h = __floats2half2_rn(acc[2 * i], acc[2 * i + 1]);
        w[i] = *(unsigned*)&h;
    }
    *(uint4*)p = u;
}

template<int LAYER>
__global__ __launch_bounds__(256, 8) void agg_kernel()
{
    const __half* __restrict__ SRC = (LAYER == 1) ? g_xh    : g_h1bh;
    __half* __restrict__       DST = (LAYER == 1) ? g_agg1h : g_agg2h;

    int tid = blockIdx.x * 256 + threadIdx.x;
    int node = tid >> 3;
    if (node >= NN) return;
    int c = (tid & 7) * 8;

    float acc[8] = {0.f, 0.f, 0.f, 0.f, 0.f, 0.f, 0.f, 0.f};
    acc_half8(acc, SRC + (size_t)node * 64 + c);   // self
    int deg = g_deg[node];
    if (deg > CAP) deg = CAP;
    const int* bkt = g_bucket + (size_t)node * CAP;

    int j = 0;
    for (; j + 3 < deg; j += 4) {
        int4 s = *(const int4*)(bkt + j);   // 16B-aligned (j%4==0, CAP%4==0)
        acc_pair_half8(acc, SRC + (size_t)s.x * 64 + c, SRC + (size_t)s.y * 64 + c);
        acc_pair_half8(acc, SRC + (size_t)s.z * 64 + c, SRC + (size_t)s.w * 64 + c);
    }
    if (j + 1 < deg) {
        int s0 = bkt[j], s1 = bkt[j + 1];
        acc_pair_half8(acc, SRC + (size_t)s0 * 64 + c, SRC + (size_t)s1 * 64 + c);
        j += 2;
    }
    if (j < deg)
        acc_half8(acc, SRC + (size_t)bkt[j] * 64 + c);
    store_half8(DST + (size_t)node * 64 + c, acc);
}

// ---------------------------------------------------------------------------
// MLP1 (wmma, 256 thr, padded smem): h1bh = fp16(relu(relu(BN(agg1@W1a+b1a))@W1b+b1b))
// ---------------------------------------------------------------------------
__global__ __launch_bounds__(256) void mlp1_kernel(
    const float* __restrict__ W1a, const float* __restrict__ b1a,
    const float* __restrict__ g1,  const float* __restrict__ be1,
    const float* __restrict__ m1,  const float* __restrict__ v1,
    const float* __restrict__ W1b, const float* __restrict__ b1b)
{
    extern __shared__ char smraw[];
    __half* Wa  = (__half*)smraw;              // 64 x WP
    __half* Wb  = Wa + 64 * WP;                // 64 x WP
    __half* Ah  = Wb + 64 * WP;                // 128 x WP
    float*  Mid = (float*)(Ah + 128 * WP);     // 128 x WP
    __shared__ float bias1[64], bias2[64], scl[64];

    const int tid = threadIdx.x;
    const int w   = tid >> 5;

    if (tid < 64) {
        float s = g1[tid] * rsqrtf(v1[tid] + BN_EPS);
        scl[tid]   = s;
        bias1[tid] = b1a[tid] * s + be1[tid] - m1[tid] * s;
        bias2[tid] = b1b[tid];
    }
    __syncthreads();
    for (int i = tid; i < 4096; i += 256) {
        int r = i >> 6, c = i & 63;
        Wa[r * WP + c] = __float2half(W1a[i] * scl[c]);
        Wb[r * WP + c] = __float2half(W1b[i]);
    }
    __syncthreads();

    for (int n0 = blockIdx.x * 128; n0 < NN; n0 += gridDim.x * 128) {
        #pragma unroll
        for (int i = 0; i < 4; i++) {
            int idx = tid + i * 256;
            int row = idx >> 3, q = idx & 7;
            int node = n0 + row;
            uint4 v = make_uint4(0, 0, 0, 0);
            if (node < NN) v = ((const uint4*)g_agg1h)[(size_t)node * 8 + q];
            *(uint4*)(Ah + row * WP + q * 8) = v;
        }
        __syncthreads();

        // ---- layer 1 ----
        {
            wmma::fragment<wmma::accumulator, 16, 16, 16, float> acc[4];
            #pragma unroll
            for (int c = 0; c < 4; c++) wmma::fill_fragment(acc[c], 0.f);
            #pragma unroll
            for (int kk = 0; kk < 4; kk++) {
                wmma::fragment<wmma::matrix_a, 16, 16, 16, __half, wmma::row_major> a;
                wmma::load_matrix_sync(a, Ah + (w * 16) * WP + kk * 16, WP);
                #pragma unroll
                for (int c = 0; c < 4; c++) {
                    wmma::fragment<wmma::matrix_b, 16, 16, 16, __half, wmma::row_major> b;
                    wmma::load_matrix_sync(b, Wa + (kk * 16) * WP + c * 16, WP);
                    wmma::mma_sync(acc[c], a, b, acc[c]);
                }
            }
            #pragma unroll
            for (int c = 0; c < 4; c++)
                wmma::store_matrix_sync(Mid + (w * 16) * WP + c * 16, acc[c],
                                        WP, wmma::mem_row_major);
        }
        __syncthreads();

        // bias + relu + fp16 -> Ah
        #pragma unroll
        for (int i = 0; i < 16; i++) {
            int s = tid + i * 256;
            int row = s >> 5, col2 = s & 31;
            float lo = fmaxf(Mid[row * WP + 2 * col2]     + bias1[2 * col2],     0.f);
            float hi = fmaxf(Mid[row * WP + 2 * col2 + 1] + bias1[2 * col2 + 1], 0.f);
            *(__half2*)(Ah + row * WP + 2 * col2) = __floats2half2_rn(lo, hi);
        }
        __syncthreads();

        // ---- layer 2 ----
        {
            wmma::fragment<wmma::accumulator, 16, 16, 16, float> acc[4];
            #pragma unroll
            for (int c = 0; c < 4; c++) wmma::fill_fragment(acc[c], 0.f);
            #pragma unroll
            for (int kk = 0; kk < 4; kk++) {
                wmma::fragment<wmma::matrix_a, 16, 16, 16, __half, wmma::row_major> a;
                wmma::load_matrix_sync(a, Ah + (w * 16) * WP + kk * 16, WP);
                #pragma unroll
                for (int c = 0; c < 4; c++) {
                    wmma::fragment<wmma::matrix_b, 16, 16, 16, __half, wmma::row_major> b;
                    wmma::load_matrix_sync(b, Wb + (kk * 16) * WP + c * 16, WP);
                    wmma::mma_sync(acc[c], a, b, acc[c]);
                }
            }
            #pragma unroll
            for (int c = 0; c < 4; c++)
                wmma::store_matrix_sync(Mid + (w * 16) * WP + c * 16, acc[c],
                                        WP, wmma::mem_row_major);
        }
        __syncthreads();

        // epilogue: bias + relu -> fp16 gmem
        #pragma unroll
        for (int i = 0; i < 16; i++) {
            int s = tid + i * 256;
            int row = s >> 5, col2 = s & 31;
            int node = n0 + row;
            if (node < NN) {
                float lo = fmaxf(Mid[row * WP + 2 * col2]     + bias2[2 * col2],     0.f);
                float hi = fmaxf(Mid[row * WP + 2 * col2 + 1] + bias2[2 * col2 + 1], 0.f);
                ((__half2*)g_h1bh)[(size_t)node * 32 + col2] = __floats2half2_rn(lo, hi);
            }
        }
        __syncthreads();
    }
}

// ---------------------------------------------------------------------------
// MLP2 (wmma, 256 thr, padded smem) + pooling
// ---------------------------------------------------------------------------
__global__ __launch_bounds__(256) void mlp2_kernel(
    const float* __restrict__ W2, const float* __restrict__ b2,
    const float* __restrict__ g2, const float* __restrict__ be2,
    const float* __restrict__ m2, const float* __restrict__ v2,
    const int* __restrict__ batch)
{
    extern __shared__ char smraw[];
    __half* Ws  = (__half*)smraw;              // 64 x WP
    __half* Ah  = Ws + 64 * WP;                // 128 x WP
    float*  Mid = (float*)(Ah + 128 * WP);     // 128 x WP
    __shared__ float bias[64], scl[64];

    const int tid = threadIdx.x;
    const int w   = tid >> 5;

    if (tid < 64) {
        float s = g2[tid] * rsqrtf(v2[tid] + BN_EPS);
        scl[tid]  = s;
        bias[tid] = b2[tid] * s + be2[tid] - m2[tid] * s;
    }
    __syncthreads();
    for (int i = tid; i < 4096; i += 256) {
        int r = i >> 6, c = i & 63;
        Ws[r * WP + c] = __float2half(W2[i] * scl[c]);
    }
    __syncthreads();

    for (int n0 = blockIdx.x * 128; n0 < NN; n0 += gridDim.x * 128) {
        #pragma unroll
        for (int i = 0; i < 4; i++) {
            int idx = tid + i * 256;
            int row = idx >> 3, q = idx & 7;
            int node = n0 + row;
            uint4 v = make_uint4(0, 0, 0, 0);
            if (node < NN) v = ((const uint4*)g_agg2h)[(size_t)node * 8 + q];
            *(uint4*)(Ah + row * WP + q * 8) = v;
        }
        __syncthreads();

        {
            wmma::fragment<wmma::accumulator, 16, 16, 16, float> acc[4];
            #pragma unroll
            for (int c = 0; c < 4; c++) wmma::fill_fragment(acc[c], 0.f);
            #pragma unroll
            for (int kk = 0; kk < 4; kk++) {
                wmma::fragment<wmma::matrix_a, 16, 16, 16, __half, wmma::row_major> a;
                wmma::load_matrix_sync(a, Ah + (w * 16) * WP + kk * 16, WP);
                #pragma unroll
                for (int c = 0; c < 4; c++) {
                    wmma::fragment<wmma::matrix_b, 16, 16, 16, __half, wmma::row_major> b;
                    wmma::load_matrix_sync(b, Ws + (kk * 16) * WP + c * 16, WP);
                    wmma::mma_sync(acc[c], a, b, acc[c]);
                }
            }
            #pragma unroll
            for (int c = 0; c < 4; c++)
                wmma::store_matrix_sync(Mid + (w * 16) * WP + c * 16, acc[c],
                                        WP, wmma::mem_row_major);
        }
        __syncthreads();

        // pooling epilogue: bias + relu -> red.add float4
        #pragma unroll
        for (int i = 0; i < 8; i++) {
            int s = tid + i * 256;
            int row = s >> 4, fq = s & 15;
            int node = n0 + row;
            if (node < NN) {
                const float* m = Mid + row * WP + fq * 4;
                float4 v;
                v.x = fmaxf(m[0] + bias[fq * 4],     0.f);
                v.y = fmaxf(m[1] + bias[fq * 4 + 1], 0.f);
                v.z = fmaxf(m[2] + bias[fq * 4 + 2], 0.f);
                v.w = fmaxf(m[3] + bias[fq * 4 + 3], 0.f);
                int g = batch[node];
                red_add_v4(g_xstruct + (size_t)g * 64 + fq * 4, v);
            }
        }
        __syncthreads();
    }
}

// ---------------------------------------------------------------------------
// K6: x_topo = relu(topo @ Wt + bt); out = [xstruct, x_topo] @ Wc + bc
// ---------------------------------------------------------------------------
__global__ __launch_bounds__(256) void final_kernel(
    const float* __restrict__ topo, const float* __restrict__ Wt,
    const float* __restrict__ bt,   const float* __restrict__ Wc,
    const float* __restrict__ bc,   float* __restrict__ out)
{
    __shared__ float Wts[64 * 64];
    __shared__ float Wcs[128 * CC];
    __shared__ float bts[64], bcs[CC];
    __shared__ float trow[4][64];
    __shared__ float xt[4][64];
    __shared__ float xs[4][64];

    const int tx = threadIdx.x;
    const int ty = threadIdx.y;
    const int tid = ty * 64 + tx;

    for (int i = tid; i < 4096; i += 256) Wts[i] = Wt[i];
    for (int i = tid; i < 128 * CC; i += 256) Wcs[i] = Wc[i];
    if (tid < 64) bts[tid] = bt[tid];
    if (tid < CC) bcs[tid] = bc[tid];
    __syncthreads();

    for (int g0 = blockIdx.x * 4; g0 < BB; g0 += gridDim.x * 4) {
        int g = g0 + ty;
        bool valid = g < BB;
        if (valid) {
            trow[ty][tx] = topo[g * 64 + tx];
            xs[ty][tx]   = g_xstruct[g * 64 + tx];
        }
        __syncthreads();
        if (valid) {
            float acc = bts[tx];
            #pragma unroll 16
            for (int k = 0; k < 64; k++)
                acc += trow[ty][k] * Wts[k * 64 + tx];
            xt[ty][tx] = fmaxf(acc, 0.f);
        }
        __syncthreads();
        if (valid && tx < CC) {
            float acc = bcs[tx];
            #pragma unroll 16
            for (int k = 0; k < 64; k++) {
                acc += xs[ty][k] * Wcs[k * CC + tx];
                acc += xt[ty][k] * Wcs[(64 + k) * CC + tx];
            }
            out[g * CC + tx] = acc;
        }
        __syncthreads();
    }
}

// ---------------------------------------------------------------------------
extern "C" void kernel_launch(void* const* d_in, const int* in_sizes, int n_in,
                              void* d_out, int out_size) {
    const float* x    = (const float*)d_in[0];
    const int*   ei   = (const int*)d_in[1];
    const int*   batch= (const int*)d_in[2];
    const float* topo = (const float*)d_in[3];
    const float* W1a  = (const float*)d_in[4];
    const float* b1a  = (const float*)d_in[5];
    const float* g1   = (const float*)d_in[6];
    const float* be1  = (const float*)d_in[7];
    const float* m1   = (const float*)d_in[8];
    const float* v1   = (const float*)d_in[9];
    const float* W1b  = (const float*)d_in[10];
    const float* b1b  = (const float*)d_in[11];
    const float* W2   = (const float*)d_in[12];
    const float* b2   = (const float*)d_in[13];
    const float* g2   = (const float*)d_in[14];
    const float* be2  = (const float*)d_in[15];
    const float* m2   = (const float*)d_in[16];
    const float* v2   = (const float*)d_in[17];
    const float* Wt   = (const float*)d_in[18];
    const float* bt   = (const float*)d_in[19];
    const float* Wc   = (const float*)d_in[20];
    const float* bc   = (const float*)d_in[21];
    float* out = (float*)d_out;

    const int smem1 = (64 * WP * 2 + 128 * WP) * 2 + 128 * WP * 4;  // ~74 KB
    const int smem2 = (64 * WP + 128 * WP) * 2 + 128 * WP * 4;      // ~65 KB

    static cudaStream_t s2;
    static cudaEvent_t evFork, evJoin;
    static bool init_done = false;
    if (!init_done) {
        cudaFuncSetAttribute(mlp1_kernel,
                             cudaFuncAttributeMaxDynamicSharedMemorySize, smem1);
        cudaFuncSetAttribute(mlp2_kernel,
                             cudaFuncAttributeMaxDynamicSharedMemorySize, smem2);
        cudaStreamCreateWithFlags(&s2, cudaStreamNonBlocking);
        cudaEventCreateWithFlags(&evFork, cudaEventDisableTiming);
        cudaEventCreateWithFlags(&evJoin, cudaEventDisableTiming);
        init_done = true;
    }

    const int NB = (NN + 255) / 256;   // 391
    dim3 finBlock(64, 4);

    // Fork: fp16 conversion of x runs concurrently with bucket build
    cudaEventRecord(evFork, 0);
    cudaStreamWaitEvent(s2, evFork, 0);
    convert_kernel<<<(NN * HH / 4 + 255) / 256, 256, 0, s2>>>(x);
    cudaEventRecord(evJoin, s2);

    // Bucket build (main stream): zero -> fill
    zero_kernel<<<NB, 256>>>();
    fill_kernel<<<(EE + 255) / 256, 256>>>(ei);

    // Join before layer 1 (needs g_xh + buckets)
    cudaStreamWaitEvent(0, evJoin, 0);

    // Layer 1
    agg_kernel<1><<<(NN * 8 + 255) / 256, 256>>>();
    mlp1_kernel<<<782, 256, smem1>>>(W1a, b1a, g1, be1, m1, v1, W1b, b1b);

    // Layer 2
    agg_kernel<2><<<(NN * 8 + 255) / 256, 256>>>();
    mlp2_kernel<<<782, 256, smem2>>>(W2, b2, g2, be2, m2, v2, batch);

    final_kernel<<<64, finBlock>>>(topo, Wt, bt, Wc, bc, out);
}